// round 3
// baseline (speedup 1.0000x reference)
#include <cuda_runtime.h>
#include <cuda_bf16.h>
#include <math.h>
#include <stdint.h>

#define Bn    256
#define Tn    512
#define Dn    512
#define Hn    512
#define H3    1536
#define DICTn 1024
#define Qn    32
#define BT    (Bn*Tn)
#define NSAMP (Bn*Qn*DICTn)   // 8388608

// ---------------- static device scratch (no runtime allocation) -------------
__device__ float g_GI[(size_t)BT * H3];          // x @ W_ih^T + b_ih
__device__ float g_h[2][Bn * Hn];                // hidden double buffer
__device__ float g_c1[Bn * Hn];
__device__ float g_c2[Bn * Hn];
__device__ float g_logits[(size_t)Bn * Qn * DICTn];
__device__ float g_gumbel[(size_t)NSAMP];

// ---------------- threefry2x32-20 (JAX-exact) --------------------------------
__host__ __device__ inline void threefry2x32(unsigned k0, unsigned k1,
                                             unsigned x0, unsigned x1,
                                             unsigned* o0, unsigned* o1) {
    unsigned ks2 = k0 ^ k1 ^ 0x1BD11BDAu;
    x0 += k0; x1 += k1;
#define TF_R(r) { x0 += x1; x1 = (x1 << (r)) | (x1 >> (32-(r))); x1 ^= x0; }
    TF_R(13) TF_R(15) TF_R(26) TF_R(6)   x0 += k1;  x1 += ks2 + 1u;
    TF_R(17) TF_R(29) TF_R(16) TF_R(24)  x0 += ks2; x1 += k0  + 2u;
    TF_R(13) TF_R(15) TF_R(26) TF_R(6)   x0 += k0;  x1 += k1  + 3u;
    TF_R(17) TF_R(29) TF_R(16) TF_R(24)  x0 += k1;  x1 += ks2 + 4u;
    TF_R(13) TF_R(15) TF_R(26) TF_R(6)   x0 += ks2; x1 += k0  + 5u;
#undef TF_R
    *o0 = x0; *o1 = x1;
}

__device__ __forceinline__ unsigned tf32r(float v) {
    unsigned o; asm("cvt.rna.tf32.f32 %0, %1;" : "=r"(o) : "f"(v)); return o;
}

// ---------------- accurate fp32 exp/log (immune to -use_fast_math) -----------
__device__ __forceinline__ float exp_acc(float x) {
    x = fminf(fmaxf(x, -80.f), 80.f);
    float n = rintf(x * 1.4426950408889634f);
    float r = fmaf(n, -0.6931471824645996f, x);
    r = fmaf(n, 1.9046542121259063e-9f, r);
    float p = 1.984126984e-4f;                  // 1/5040
    p = fmaf(p, r, 1.388888889e-3f);            // 1/720
    p = fmaf(p, r, 8.333333333e-3f);            // 1/120
    p = fmaf(p, r, 4.166666667e-2f);            // 1/24
    p = fmaf(p, r, 1.666666667e-1f);            // 1/6
    p = fmaf(p, r, 0.5f);
    p = fmaf(p, r, 1.0f);
    p = fmaf(p, r, 1.0f);
    int ni = (int)n;
    float sc = __int_as_float((ni + 127) << 23);
    return p * sc;
}

__device__ __forceinline__ float log_acc(float x) {
    int xi = __float_as_int(x);
    int e = ((xi >> 23) & 0xff) - 127;
    float m = __int_as_float((xi & 0x7fffff) | 0x3f800000);
    if (m > 1.4142135623730951f) { m *= 0.5f; e += 1; }
    float fe = (float)e;
    float s = __fdiv_rn(m - 1.0f, m + 1.0f);
    float s2 = s * s;
    float p = 0.111111111f;                     // 1/9
    p = fmaf(p, s2, 0.142857143f);              // 1/7
    p = fmaf(p, s2, 0.2f);                      // 1/5
    p = fmaf(p, s2, 0.333333333f);              // 1/3
    p = p * s2;
    float logm = fmaf(2.0f * s, p, 2.0f * s);
    float res = fmaf(fe, 0.6931471824645996f, logm);
    res = fmaf(fe, -1.9046542121259063e-9f, res);
    return res;
}

__device__ __forceinline__ float sigmoid_acc(float x) {
    return __fdiv_rn(1.0f, 1.0f + exp_acc(-x));
}
__device__ __forceinline__ float tanh_acc(float x) {
    float a = fabsf(x);
    float e = exp_acc(-2.0f * a);
    float t = __fdiv_rn(1.0f - e, 1.0f + e);
    return copysignf(t, x);
}

// ---------------- 3xTF32 GEMM: C[M,N] = A[M,K]*B[N,K]^T + bias ---------------
// 128(M) x 64(N) block tile, 8 warps (4x2), warp tile 32x32, K chunk 32.
__global__ __launch_bounds__(256, 2)
void gemm_f32(const float* __restrict__ A, int lda,
              const float* __restrict__ Bm, int ldb,
              float* __restrict__ C, int ldc,
              int K, const float* __restrict__ bias, int relu)
{
    __shared__ unsigned As_h[128][32], As_l[128][32];
    __shared__ unsigned Bs_h[64][32],  Bs_l[64][32];

    const int tid  = threadIdx.x;
    const int warp = tid >> 5, lane = tid & 31;
    const int g    = lane >> 2, tig = lane & 3;
    const int m0   = blockIdx.y * 128, n0 = blockIdx.x * 64;
    const int wm   = (warp >> 1) * 32, wn = (warp & 1) * 32;

    float acc[2][4][4];
#pragma unroll
    for (int mi = 0; mi < 2; mi++)
#pragma unroll
        for (int ni = 0; ni < 4; ni++)
#pragma unroll
            for (int r = 0; r < 4; r++) acc[mi][ni][r] = 0.f;

    float ra[16], rb[8];
#pragma unroll
    for (int i = 0; i < 16; i++) {
        int idx = tid + i * 256; int m = idx >> 5, k = idx & 31;
        ra[i] = A[(size_t)(m0 + m) * lda + k];
    }
#pragma unroll
    for (int i = 0; i < 8; i++) {
        int idx = tid + i * 256; int n = idx >> 5, k = idx & 31;
        rb[i] = Bm[(size_t)(n0 + n) * ldb + k];
    }

    const int nchunk = K >> 5;
    for (int ch = 0; ch < nchunk; ch++) {
#pragma unroll
        for (int i = 0; i < 16; i++) {
            int idx = tid + i * 256; int m = idx >> 5, k = (idx & 31) ^ ((( idx >> 5) & 7) << 2);
            unsigned hi = tf32r(ra[i]);
            As_h[m][k] = hi;
            As_l[m][k] = tf32r(ra[i] - __uint_as_float(hi));
        }
#pragma unroll
        for (int i = 0; i < 8; i++) {
            int idx = tid + i * 256; int n = idx >> 5, k = (idx & 31) ^ (((idx >> 5) & 7) << 2);
            unsigned hi = tf32r(rb[i]);
            Bs_h[n][k] = hi;
            Bs_l[n][k] = tf32r(rb[i] - __uint_as_float(hi));
        }
        __syncthreads();

        if (ch + 1 < nchunk) {
            int k0 = (ch + 1) << 5;
#pragma unroll
            for (int i = 0; i < 16; i++) {
                int idx = tid + i * 256; int m = idx >> 5, k = idx & 31;
                ra[i] = A[(size_t)(m0 + m) * lda + k0 + k];
            }
#pragma unroll
            for (int i = 0; i < 8; i++) {
                int idx = tid + i * 256; int n = idx >> 5, k = idx & 31;
                rb[i] = Bm[(size_t)(n0 + n) * ldb + k0 + k];
            }
        }

#pragma unroll
        for (int kk = 0; kk < 32; kk += 8) {
            unsigned ah[2][4], al[2][4], bh[4][2], bl[4][2];
#pragma unroll
            for (int mi = 0; mi < 2; mi++) {
                int r0 = wm + mi * 16;
                int c0k = (kk + tig) ^ (g << 2), c1k = (kk + tig + 4) ^ (g << 2);
                ah[mi][0] = As_h[r0 + g    ][c0k]; al[mi][0] = As_l[r0 + g    ][c0k];
                ah[mi][1] = As_h[r0 + g + 8][c0k]; al[mi][1] = As_l[r0 + g + 8][c0k];
                ah[mi][2] = As_h[r0 + g    ][c1k]; al[mi][2] = As_l[r0 + g    ][c1k];
                ah[mi][3] = As_h[r0 + g + 8][c1k]; al[mi][3] = As_l[r0 + g + 8][c1k];
            }
#pragma unroll
            for (int ni = 0; ni < 4; ni++) {
                int nrow = wn + ni * 8 + g;
                int c0k = (kk + tig) ^ (g << 2), c1k = (kk + tig + 4) ^ (g << 2);
                bh[ni][0] = Bs_h[nrow][c0k]; bl[ni][0] = Bs_l[nrow][c0k];
                bh[ni][1] = Bs_h[nrow][c1k]; bl[ni][1] = Bs_l[nrow][c1k];
            }
#define MMA(ACC, A0,A1,A2,A3, B0,B1)                                          \
            asm volatile(                                                     \
                "mma.sync.aligned.m16n8k8.row.col.f32.tf32.tf32.f32 "         \
                "{%0,%1,%2,%3}, {%4,%5,%6,%7}, {%8,%9}, {%0,%1,%2,%3};\n"     \
                : "+f"(ACC[0]), "+f"(ACC[1]), "+f"(ACC[2]), "+f"(ACC[3])      \
                : "r"(A0), "r"(A1), "r"(A2), "r"(A3), "r"(B0), "r"(B1))
#pragma unroll
            for (int mi = 0; mi < 2; mi++)
#pragma unroll
                for (int ni = 0; ni < 4; ni++) {
                    MMA(acc[mi][ni], ah[mi][0],ah[mi][1],ah[mi][2],ah[mi][3], bl[ni][0],bl[ni][1]);
                    MMA(acc[mi][ni], al[mi][0],al[mi][1],al[mi][2],al[mi][3], bh[ni][0],bh[ni][1]);
                    MMA(acc[mi][ni], ah[mi][0],ah[mi][1],ah[mi][2],ah[mi][3], bh[ni][0],bh[ni][1]);
                }
        }
        __syncthreads();
    }

#pragma unroll
    for (int mi = 0; mi < 2; mi++)
#pragma unroll
        for (int ni = 0; ni < 4; ni++) {
            int r = m0 + wm + mi * 16 + g;
            int c = n0 + wn + ni * 8 + tig * 2;
            float b0 = bias ? bias[c]     : 0.f;
            float b1 = bias ? bias[c + 1] : 0.f;
            float v0 = acc[mi][ni][0] + b0;
            float v1 = acc[mi][ni][1] + b1;
            float v2 = acc[mi][ni][2] + b0;
            float v3 = acc[mi][ni][3] + b1;
            if (relu) { v0 = fmaxf(v0, 0.f); v1 = fmaxf(v1, 0.f);
                        v2 = fmaxf(v2, 0.f); v3 = fmaxf(v3, 0.f); }
            C[(size_t)r * ldc + c]           = v0;
            C[(size_t)r * ldc + c + 1]       = v1;
            C[(size_t)(r + 8) * ldc + c]     = v2;
            C[(size_t)(r + 8) * ldc + c + 1] = v3;
        }
}

// ---------------- fused GRU step (3xTF32 GEMM tile + gate math) --------------
// Block: 32 rows (batch) x 64 hidden cols (=> 192 gh cols), 8 warps (2x4).
// dynamic smem layout (unsigned words):
//   [0,1024)      As_h   32x32
//   [1024,2048)   As_l
//   [2048,8192)   Bs_h   192x32
//   [8192,14336)  Bs_l
//   [14336,20480) gh_s (float) 32x192
__global__ __launch_bounds__(256)
void gru_step(const float* __restrict__ GI, const float* __restrict__ W_hh,
              const float* __restrict__ b_hh, const int* __restrict__ lengths,
              const float* __restrict__ h_in, float* __restrict__ h_out, int t)
{
    extern __shared__ unsigned dyn[];
    unsigned* As_h = dyn;
    unsigned* As_l = dyn + 1024;
    unsigned* Bs_h = dyn + 2048;
    unsigned* Bs_l = dyn + 8192;
    float*    gh_s = (float*)(dyn + 14336);

    const int tid  = threadIdx.x;
    const int warp = tid >> 5, lane = tid & 31;
    const int g    = lane >> 2, tig = lane & 3;
    const int c0   = blockIdx.x * 64;
    const int m0   = blockIdx.y * 32;
    const int wm   = (warp >> 2) * 16;
    const int wn   = (warp & 3) * 48;

    float acc[6][4];
#pragma unroll
    for (int ni = 0; ni < 6; ni++)
#pragma unroll
        for (int r = 0; r < 4; r++) acc[ni][r] = 0.f;

    float ra[4], rb[24];
#pragma unroll
    for (int i = 0; i < 4; i++) {
        int idx = tid + i * 256; int m = idx >> 5, k = idx & 31;
        ra[i] = h_in[(m0 + m) * Hn + k];
    }
#pragma unroll
    for (int i = 0; i < 24; i++) {
        int idx = tid + i * 256; int n = idx >> 5, k = idx & 31;
        int wrow = (n >> 6) * Hn + c0 + (n & 63);
        rb[i] = W_hh[(size_t)wrow * Hn + k];
    }

    for (int ch = 0; ch < 16; ch++) {
#pragma unroll
        for (int i = 0; i < 4; i++) {
            int idx = tid + i * 256; int m = idx >> 5;
            int k = (idx & 31) ^ ((m & 7) << 2);
            unsigned hi = tf32r(ra[i]);
            As_h[m * 32 + k] = hi;
            As_l[m * 32 + k] = tf32r(ra[i] - __uint_as_float(hi));
        }
#pragma unroll
        for (int i = 0; i < 24; i++) {
            int idx = tid + i * 256; int n = idx >> 5;
            int k = (idx & 31) ^ ((n & 7) << 2);
            unsigned hi = tf32r(rb[i]);
            Bs_h[n * 32 + k] = hi;
            Bs_l[n * 32 + k] = tf32r(rb[i] - __uint_as_float(hi));
        }
        __syncthreads();

        if (ch + 1 < 16) {
            int k0 = (ch + 1) << 5;
#pragma unroll
            for (int i = 0; i < 4; i++) {
                int idx = tid + i * 256; int m = idx >> 5, k = idx & 31;
                ra[i] = h_in[(m0 + m) * Hn + k0 + k];
            }
#pragma unroll
            for (int i = 0; i < 24; i++) {
                int idx = tid + i * 256; int n = idx >> 5, k = idx & 31;
                int wrow = (n >> 6) * Hn + c0 + (n & 63);
                rb[i] = W_hh[(size_t)wrow * Hn + k0 + k];
            }
        }

#pragma unroll
        for (int kk = 0; kk < 32; kk += 8) {
            int c0k = (kk + tig) ^ (g << 2), c1k = (kk + tig + 4) ^ (g << 2);
            unsigned ah[4], al[4], bh[6][2], bl[6][2];
            ah[0] = As_h[(wm + g    ) * 32 + c0k]; al[0] = As_l[(wm + g    ) * 32 + c0k];
            ah[1] = As_h[(wm + g + 8) * 32 + c0k]; al[1] = As_l[(wm + g + 8) * 32 + c0k];
            ah[2] = As_h[(wm + g    ) * 32 + c1k]; al[2] = As_l[(wm + g    ) * 32 + c1k];
            ah[3] = As_h[(wm + g + 8) * 32 + c1k]; al[3] = As_l[(wm + g + 8) * 32 + c1k];
#pragma unroll
            for (int ni = 0; ni < 6; ni++) {
                int nrow = wn + ni * 8 + g;
                bh[ni][0] = Bs_h[nrow * 32 + c0k]; bl[ni][0] = Bs_l[nrow * 32 + c0k];
                bh[ni][1] = Bs_h[nrow * 32 + c1k]; bl[ni][1] = Bs_l[nrow * 32 + c1k];
            }
#pragma unroll
            for (int ni = 0; ni < 6; ni++) {
                MMA(acc[ni], ah[0],ah[1],ah[2],ah[3], bl[ni][0],bl[ni][1]);
                MMA(acc[ni], al[0],al[1],al[2],al[3], bh[ni][0],bh[ni][1]);
                MMA(acc[ni], ah[0],ah[1],ah[2],ah[3], bh[ni][0],bh[ni][1]);
            }
        }
        __syncthreads();
    }

#pragma unroll
    for (int ni = 0; ni < 6; ni++) {
        int r = wm + g;
        int c = wn + ni * 8 + tig * 2;
        gh_s[r * 192 + c]           = acc[ni][0];
        gh_s[r * 192 + c + 1]       = acc[ni][1];
        gh_s[(r + 8) * 192 + c]     = acc[ni][2];
        gh_s[(r + 8) * 192 + c + 1] = acc[ni][3];
    }
    __syncthreads();

#pragma unroll
    for (int i = 0; i < 8; i++) {
        int idx = tid + i * 256;
        int mr = idx >> 6, j = idx & 63;
        int b = m0 + mr, jj = c0 + j;
        const float* gi = GI + ((size_t)b * Tn + t) * H3;
        float gir = gi[jj];
        float giz = gi[Hn + jj];
        float gin = gi[2 * Hn + jj];
        float ghr = gh_s[mr * 192 + j]       + b_hh[jj];
        float ghz = gh_s[mr * 192 + 64 + j]  + b_hh[Hn + jj];
        float ghn = gh_s[mr * 192 + 128 + j] + b_hh[2 * Hn + jj];
        float r = sigmoid_acc(gir + ghr);
        float z = sigmoid_acc(giz + ghz);
        float n = tanh_acc(fmaf(r, ghn, gin));
        float ho = h_in[b * Hn + jj];
        float hn = (1.f - z) * n + z * ho;
        h_out[b * Hn + jj] = (t < lengths[b]) ? hn : ho;
    }
}

// ---------------- misc -------------------------------------------------------
__global__ void zero_kernel(float* p, int n) {
    int i = blockIdx.x * blockDim.x + threadIdx.x;
    if (i < n) p[i] = 0.f;
}

__global__ void value_kernel(const float* __restrict__ h2,
                             const float* __restrict__ Wc3,
                             const float* __restrict__ bc3,
                             float* __restrict__ out)
{
    int gw = (blockIdx.x * blockDim.x + threadIdx.x) >> 5;
    int lane = threadIdx.x & 31;
    if (gw >= Bn) return;
    float s = 0.f;
    for (int k = lane; k < Hn; k += 32) s = fmaf(h2[gw * Hn + k], Wc3[k], s);
#pragma unroll
    for (int o = 16; o; o >>= 1) s += __shfl_xor_sync(0xffffffffu, s, o);
    if (lane == 0) out[gw] = s + bc3[0];
}

// partitionable threefry bits: counter = flat index (hi=0 for i < 2^32),
// bits = out0 ^ out1 (JAX _threefry_random_bits_partitionable, 32-bit path)
__global__ void gumbel_kernel(unsigned k0, unsigned k1, float* __restrict__ gout)
{
    unsigned i = blockIdx.x * blockDim.x + threadIdx.x;   // 0 .. 2^23-1
    unsigned o0, o1;
    threefry2x32(k0, k1, 0u, i, &o0, &o1);
    unsigned bits = o0 ^ o1;
    float f = __uint_as_float((bits >> 9) | 0x3f800000u) - 1.0f;
    float u = fmaxf(f, 1.17549435e-38f);
    float g = -log_acc(-log_acc(u));
    gout[i] = g;
}

__global__ __launch_bounds__(256)
void sample_kernel(const float* __restrict__ logits,
                   const float* __restrict__ gumbel,
                   float* __restrict__ out_query,
                   float* __restrict__ out_lp)
{
    __shared__ float red[256];
    __shared__ int   redi[256];
    int row = blockIdx.x;
    int tid = threadIdx.x;
    const float* lg = logits + (size_t)row * DICTn;
    const float* gm = gumbel + (size_t)row * DICTn;

    float l[4];
#pragma unroll
    for (int i = 0; i < 4; i++) l[i] = lg[tid + i * 256];

    float mx = fmaxf(fmaxf(l[0], l[1]), fmaxf(l[2], l[3]));
    red[tid] = mx; __syncthreads();
    for (int s = 128; s > 0; s >>= 1) {
        if (tid < s) red[tid] = fmaxf(red[tid], red[tid + s]);
        __syncthreads();
    }
    mx = red[0]; __syncthreads();

    float se = 0.f;
#pragma unroll
    for (int i = 0; i < 4; i++) se += exp_acc(l[i] - mx);
    red[tid] = se; __syncthreads();
    for (int s = 128; s > 0; s >>= 1) {
        if (tid < s) red[tid] += red[tid + s];
        __syncthreads();
    }
    float logZ = mx + log_acc(red[0]); __syncthreads();

    float bv = -1e30f; int bi = 0x7fffffff;
#pragma unroll
    for (int i = 0; i < 4; i++) {
        int idx = tid + i * 256;
        float lp = l[i] - logZ;
        out_lp[(size_t)row * DICTn + idx] = lp;
        float v = lp + gm[idx];
        if (v > bv || (v == bv && idx < bi)) { bv = v; bi = idx; }
    }
    red[tid] = bv; redi[tid] = bi; __syncthreads();
    for (int s = 128; s > 0; s >>= 1) {
        if (tid < s) {
            if (red[tid + s] > red[tid] ||
                (red[tid + s] == red[tid] && redi[tid + s] < redi[tid])) {
                red[tid] = red[tid + s]; redi[tid] = redi[tid + s];
            }
        }
        __syncthreads();
    }
    int win = redi[0];
#pragma unroll
    for (int i = 0; i < 4; i++) {
        int idx = tid + i * 256;
        out_query[(size_t)row * DICTn + idx] = (idx == win) ? 1.f : 0.f;
    }
}

// ---------------- host -------------------------------------------------------
extern "C" void kernel_launch(void* const* d_in, const int* in_sizes, int n_in,
                              void* d_out, int out_size)
{
    const float* x      = (const float*)d_in[0];
    const int*   lens   = (const int*)  d_in[1];
    const float* W_ih   = (const float*)d_in[2];
    const float* W_hh   = (const float*)d_in[3];
    const float* b_ih   = (const float*)d_in[4];
    const float* b_hh   = (const float*)d_in[5];
    const float* W_out  = (const float*)d_in[6];
    const float* b_out  = (const float*)d_in[7];
    const float* Wc1    = (const float*)d_in[8];
    const float* bc1    = (const float*)d_in[9];
    const float* Wc2    = (const float*)d_in[10];
    const float* bc2    = (const float*)d_in[11];
    const float* Wc3    = (const float*)d_in[12];
    const float* bc3    = (const float*)d_in[13];

    float* out_value = (float*)d_out;
    float* out_query = out_value + Bn;
    float* out_lp    = out_query + (size_t)NSAMP;

    float *pGI, *ph0, *ph1, *pc1, *pc2, *plog, *pgum;
    cudaGetSymbolAddress((void**)&pGI,  g_GI);
    cudaGetSymbolAddress((void**)&ph0,  g_h);
    ph1 = ph0 + Bn * Hn;
    cudaGetSymbolAddress((void**)&pc1,  g_c1);
    cudaGetSymbolAddress((void**)&pc2,  g_c2);
    cudaGetSymbolAddress((void**)&plog, g_logits);
    cudaGetSymbolAddress((void**)&pgum, g_gumbel);

    static int attr_done = 0;
    if (!attr_done) {
        cudaFuncSetAttribute(gru_step,
            cudaFuncAttributeMaxDynamicSharedMemorySize, 81920);
        attr_done = 1;
    }

    // 1) zero h
    zero_kernel<<<(Bn * Hn + 255) / 256, 256>>>(ph0, Bn * Hn);

    // 2) GI = x @ W_ih^T + b_ih   [131072, 1536]
    gemm_f32<<<dim3(H3 / 64, BT / 128), 256>>>(x, Dn, W_ih, Dn, pGI, H3,
                                               Dn, b_ih, 0);

    // 3) recurrence: 512 fused steps
    float* hbuf[2] = { ph0, ph1 };
    for (int t = 0; t < Tn; t++) {
        gru_step<<<dim3(Hn / 64, Bn / 32), 256, 81920>>>(
            pGI, W_hh, b_hh, lens, hbuf[t & 1], hbuf[(t + 1) & 1], t);
    }
    float* hfin = hbuf[Tn & 1];

    // 4) critic
    gemm_f32<<<dim3(Hn / 64, Bn / 128), 256>>>(hfin, Hn, Wc1, Hn, pc1, Hn,
                                               Hn, bc1, 1);
    gemm_f32<<<dim3(Hn / 64, Bn / 128), 256>>>(pc1, Hn, Wc2, Hn, pc2, Hn,
                                               Hn, bc2, 1);
    value_kernel<<<(Bn * 32 + 255) / 256, 256>>>(pc2, Wc3, bc3, out_value);

    // 5) actor logits [256, 32768]
    gemm_f32<<<dim3(DICTn * Qn / 64, Bn / 128), 256>>>(hfin, Hn, W_out, Hn,
                                                       plog, DICTn * Qn,
                                                       Hn, b_out, 0);

    // 6) gumbel noise: skey = fold_in(key(0), 1234), partitionable bits
    unsigned s0, s1;
    threefry2x32(0u, 0u, 0u, 1234u, &s0, &s1);
    gumbel_kernel<<<NSAMP / 256, 256>>>(s0, s1, pgum);

    // 7) log-softmax + categorical sample + one-hot
    sample_kernel<<<Bn * Qn, 256>>>(plog, pgum, out_query, out_lp);
}

// round 4
// speedup vs baseline: 1.5450x; 1.5450x over previous
#include <cuda_runtime.h>
#include <cuda_bf16.h>
#include <math.h>
#include <stdint.h>

#define Bn    256
#define Tn    512
#define Dn    512
#define Hn    512
#define H3    1536
#define DICTn 1024
#define Qn    32
#define BT    (Bn*Tn)
#define NSAMP (Bn*Qn*DICTn)   // 8388608

#define NCTA_REC 128          // persistent recurrence CTAs (<=148, 1/SM)
#define WS_WORDS (48*512)     // W slice words per CTA

// ---------------- static device scratch (no runtime allocation) -------------
__device__ float g_GI[(size_t)BT * H3];          // x @ W_ih^T + b_ih
__device__ float g_h[2][Bn * Hn];                // hidden double buffer
__device__ float g_c1[Bn * Hn];
__device__ float g_c2[Bn * Hn];
__device__ float g_logits[(size_t)Bn * Qn * DICTn];
__device__ float g_gumbel[(size_t)NSAMP];
__device__ unsigned g_barrier;

// ---------------- threefry2x32-20 (JAX-exact) --------------------------------
__host__ __device__ inline void threefry2x32(unsigned k0, unsigned k1,
                                             unsigned x0, unsigned x1,
                                             unsigned* o0, unsigned* o1) {
    unsigned ks2 = k0 ^ k1 ^ 0x1BD11BDAu;
    x0 += k0; x1 += k1;
#define TF_R(r) { x0 += x1; x1 = (x1 << (r)) | (x1 >> (32-(r))); x1 ^= x0; }
    TF_R(13) TF_R(15) TF_R(26) TF_R(6)   x0 += k1;  x1 += ks2 + 1u;
    TF_R(17) TF_R(29) TF_R(16) TF_R(24)  x0 += ks2; x1 += k0  + 2u;
    TF_R(13) TF_R(15) TF_R(26) TF_R(6)   x0 += k0;  x1 += k1  + 3u;
    TF_R(17) TF_R(29) TF_R(16) TF_R(24)  x0 += k1;  x1 += ks2 + 4u;
    TF_R(13) TF_R(15) TF_R(26) TF_R(6)   x0 += ks2; x1 += k0  + 5u;
#undef TF_R
    *o0 = x0; *o1 = x1;
}

__device__ __forceinline__ unsigned tf32r(float v) {
    unsigned o; asm("cvt.rna.tf32.f32 %0, %1;" : "=r"(o) : "f"(v)); return o;
}

// ---------------- accurate fp32 exp/log (immune to -use_fast_math) -----------
__device__ __forceinline__ float exp_acc(float x) {
    x = fminf(fmaxf(x, -80.f), 80.f);
    float n = rintf(x * 1.4426950408889634f);
    float r = fmaf(n, -0.6931471824645996f, x);
    r = fmaf(n, 1.9046542121259063e-9f, r);
    float p = 1.984126984e-4f;
    p = fmaf(p, r, 1.388888889e-3f);
    p = fmaf(p, r, 8.333333333e-3f);
    p = fmaf(p, r, 4.166666667e-2f);
    p = fmaf(p, r, 1.666666667e-1f);
    p = fmaf(p, r, 0.5f);
    p = fmaf(p, r, 1.0f);
    p = fmaf(p, r, 1.0f);
    int ni = (int)n;
    float sc = __int_as_float((ni + 127) << 23);
    return p * sc;
}

__device__ __forceinline__ float log_acc(float x) {
    int xi = __float_as_int(x);
    int e = ((xi >> 23) & 0xff) - 127;
    float m = __int_as_float((xi & 0x7fffff) | 0x3f800000);
    if (m > 1.4142135623730951f) { m *= 0.5f; e += 1; }
    float fe = (float)e;
    float s = __fdiv_rn(m - 1.0f, m + 1.0f);
    float s2 = s * s;
    float p = 0.111111111f;
    p = fmaf(p, s2, 0.142857143f);
    p = fmaf(p, s2, 0.2f);
    p = fmaf(p, s2, 0.333333333f);
    p = p * s2;
    float logm = fmaf(2.0f * s, p, 2.0f * s);
    float res = fmaf(fe, 0.6931471824645996f, logm);
    res = fmaf(fe, -1.9046542121259063e-9f, res);
    return res;
}

__device__ __forceinline__ float sigmoid_acc(float x) {
    return __fdiv_rn(1.0f, 1.0f + exp_acc(-x));
}
__device__ __forceinline__ float tanh_acc(float x) {
    float a = fabsf(x);
    float e = exp_acc(-2.0f * a);
    float t = __fdiv_rn(1.0f - e, 1.0f + e);
    return copysignf(t, x);
}

#define MMA(ACC, A0,A1,A2,A3, B0,B1)                                          \
    asm volatile(                                                             \
        "mma.sync.aligned.m16n8k8.row.col.f32.tf32.tf32.f32 "                 \
        "{%0,%1,%2,%3}, {%4,%5,%6,%7}, {%8,%9}, {%0,%1,%2,%3};\n"             \
        : "+f"(ACC[0]), "+f"(ACC[1]), "+f"(ACC[2]), "+f"(ACC[3])              \
        : "r"(A0), "r"(A1), "r"(A2), "r"(A3), "r"(B0), "r"(B1))

// ---------------- 3xTF32 GEMM: C[M,N] = A[M,K]*B[N,K]^T + bias ---------------
// 128(M) x 64(N) block tile, 8 warps (4x2), warp tile 32x32, K chunk 32.
// row_lens != nullptr: rows are (b*Tn + t); skip tile if t_start >= lens[b].
__global__ __launch_bounds__(256, 2)
void gemm_f32(const float* __restrict__ A, int lda,
              const float* __restrict__ Bm, int ldb,
              float* __restrict__ C, int ldc,
              int K, const float* __restrict__ bias, int relu,
              const int* __restrict__ row_lens)
{
    __shared__ unsigned As_h[128][32], As_l[128][32];
    __shared__ unsigned Bs_h[64][32],  Bs_l[64][32];

    const int tid  = threadIdx.x;
    const int warp = tid >> 5, lane = tid & 31;
    const int g    = lane >> 2, tig = lane & 3;
    const int m0   = blockIdx.y * 128, n0 = blockIdx.x * 64;
    const int wm   = (warp >> 1) * 32, wn = (warp & 1) * 32;

    if (row_lens) {   // ragged skip: whole tile beyond this sample's length
        int b = m0 >> 9;
        int ts = m0 & 511;
        if (ts >= row_lens[b]) return;
    }

    float acc[2][4][4];
#pragma unroll
    for (int mi = 0; mi < 2; mi++)
#pragma unroll
        for (int ni = 0; ni < 4; ni++)
#pragma unroll
            for (int r = 0; r < 4; r++) acc[mi][ni][r] = 0.f;

    float ra[16], rb[8];
#pragma unroll
    for (int i = 0; i < 16; i++) {
        int idx = tid + i * 256; int m = idx >> 5, k = idx & 31;
        ra[i] = A[(size_t)(m0 + m) * lda + k];
    }
#pragma unroll
    for (int i = 0; i < 8; i++) {
        int idx = tid + i * 256; int n = idx >> 5, k = idx & 31;
        rb[i] = Bm[(size_t)(n0 + n) * ldb + k];
    }

    const int nchunk = K >> 5;
    for (int ch = 0; ch < nchunk; ch++) {
#pragma unroll
        for (int i = 0; i < 16; i++) {
            int idx = tid + i * 256; int m = idx >> 5, k = (idx & 31) ^ (((idx >> 5) & 7) << 2);
            unsigned hi = tf32r(ra[i]);
            As_h[m][k] = hi;
            As_l[m][k] = tf32r(ra[i] - __uint_as_float(hi));
        }
#pragma unroll
        for (int i = 0; i < 8; i++) {
            int idx = tid + i * 256; int n = idx >> 5, k = (idx & 31) ^ (((idx >> 5) & 7) << 2);
            unsigned hi = tf32r(rb[i]);
            Bs_h[n][k] = hi;
            Bs_l[n][k] = tf32r(rb[i] - __uint_as_float(hi));
        }
        __syncthreads();

        if (ch + 1 < nchunk) {
            int k0 = (ch + 1) << 5;
#pragma unroll
            for (int i = 0; i < 16; i++) {
                int idx = tid + i * 256; int m = idx >> 5, k = idx & 31;
                ra[i] = A[(size_t)(m0 + m) * lda + k0 + k];
            }
#pragma unroll
            for (int i = 0; i < 8; i++) {
                int idx = tid + i * 256; int n = idx >> 5, k = idx & 31;
                rb[i] = Bm[(size_t)(n0 + n) * ldb + k0 + k];
            }
        }

#pragma unroll
        for (int kk = 0; kk < 32; kk += 8) {
            unsigned ah[2][4], al[2][4], bh[4][2], bl[4][2];
#pragma unroll
            for (int mi = 0; mi < 2; mi++) {
                int r0 = wm + mi * 16;
                int c0k = (kk + tig) ^ (g << 2), c1k = (kk + tig + 4) ^ (g << 2);
                ah[mi][0] = As_h[r0 + g    ][c0k]; al[mi][0] = As_l[r0 + g    ][c0k];
                ah[mi][1] = As_h[r0 + g + 8][c0k]; al[mi][1] = As_l[r0 + g + 8][c0k];
                ah[mi][2] = As_h[r0 + g    ][c1k]; al[mi][2] = As_l[r0 + g    ][c1k];
                ah[mi][3] = As_h[r0 + g + 8][c1k]; al[mi][3] = As_l[r0 + g + 8][c1k];
            }
#pragma unroll
            for (int ni = 0; ni < 4; ni++) {
                int nrow = wn + ni * 8 + g;
                int c0k = (kk + tig) ^ (g << 2), c1k = (kk + tig + 4) ^ (g << 2);
                bh[ni][0] = Bs_h[nrow][c0k]; bl[ni][0] = Bs_l[nrow][c0k];
                bh[ni][1] = Bs_h[nrow][c1k]; bl[ni][1] = Bs_l[nrow][c1k];
            }
#pragma unroll
            for (int mi = 0; mi < 2; mi++)
#pragma unroll
                for (int ni = 0; ni < 4; ni++) {
                    MMA(acc[mi][ni], ah[mi][0],ah[mi][1],ah[mi][2],ah[mi][3], bl[ni][0],bl[ni][1]);
                    MMA(acc[mi][ni], al[mi][0],al[mi][1],al[mi][2],al[mi][3], bh[ni][0],bh[ni][1]);
                    MMA(acc[mi][ni], ah[mi][0],ah[mi][1],ah[mi][2],ah[mi][3], bh[ni][0],bh[ni][1]);
                }
        }
        __syncthreads();
    }

#pragma unroll
    for (int mi = 0; mi < 2; mi++)
#pragma unroll
        for (int ni = 0; ni < 4; ni++) {
            int r = m0 + wm + mi * 16 + g;
            int c = n0 + wn + ni * 8 + tig * 2;
            float b0 = bias ? bias[c]     : 0.f;
            float b1 = bias ? bias[c + 1] : 0.f;
            float v0 = acc[mi][ni][0] + b0;
            float v1 = acc[mi][ni][1] + b1;
            float v2 = acc[mi][ni][2] + b0;
            float v3 = acc[mi][ni][3] + b1;
            if (relu) { v0 = fmaxf(v0, 0.f); v1 = fmaxf(v1, 0.f);
                        v2 = fmaxf(v2, 0.f); v3 = fmaxf(v3, 0.f); }
            C[(size_t)r * ldc + c]           = v0;
            C[(size_t)r * ldc + c + 1]       = v1;
            C[(size_t)(r + 8) * ldc + c]     = v2;
            C[(size_t)(r + 8) * ldc + c + 1] = v3;
        }
}

// ---------------- persistent GRU recurrence ----------------------------------
// 128 CTAs = 4 batch-groups(64 rows) x 32 col-groups(16 hidden cols -> 48 gh).
// W_hh slice (hi/lo tf32, swizzled) resident in SMEM for all 512 steps.
// Per step: h tile streamed via double-buffered raw-fp32 SMEM, hi/lo split in
// registers, 3xTF32 mma.sync, gate math, write h slice, grid barrier.
__global__ __launch_bounds__(256, 1)
void gru_persistent(const float* __restrict__ GI,
                    const float* __restrict__ W_hh,
                    const float* __restrict__ b_hh,
                    const int*   __restrict__ lengths,
                    float* __restrict__ hbase,
                    unsigned* __restrict__ bar)
{
    extern __shared__ unsigned smem[];
    unsigned* Ws_h = smem;                        // 48*512
    unsigned* Ws_l = smem + WS_WORDS;             // 48*512
    float*    Abuf = (float*)(smem + 2 * WS_WORDS);  // 2 x 2048 floats
    float*    gh_s = Abuf;                        // 64x48, reused after K loop

    const int tid  = threadIdx.x;
    const int warp = tid >> 5, lane = tid & 31;
    const int g    = lane >> 2, tig = lane & 3;
    const int cgp  = blockIdx.x & 31;
    const int bg   = blockIdx.x >> 5;
    const int m0   = bg * 64;
    const int jj0  = cgp * 16;
    const int wm   = (warp >> 1) * 16;            // 0,16,32,48
    const int wn   = (warp & 1) * 24;             // 0,24
    const unsigned nc = gridDim.x;

    // ---- one-time W slice preload: rows n = gate*16+c -> W_hh[gate*512+jj0+c]
    for (int i = tid; i < WS_WORDS; i += 256) {
        int n = i >> 9, k = i & 511;
        int wrow = (n >> 4) * Hn + jj0 + (n & 15);
        float w = W_hh[(size_t)wrow * Hn + k];
        unsigned hi = tf32r(w);
        int off = (n << 9) + (k & ~31) + ((k & 31) ^ ((n & 7) << 2));
        Ws_h[off] = hi;
        Ws_l[off] = tf32r(w - __uint_as_float(hi));
    }
    __syncthreads();

    for (int t = 0; t < Tn; t++) {
        const float* h_in  = hbase + (t & 1) * (Bn * Hn);
        float*       h_out = hbase + ((t + 1) & 1) * (Bn * Hn);

        float acc[3][4];
#pragma unroll
        for (int ni = 0; ni < 3; ni++)
#pragma unroll
            for (int r = 0; r < 4; r++) acc[ni][r] = 0.f;

        float ra[8];
#pragma unroll
        for (int i = 0; i < 8; i++) {
            int idx = tid + i * 256; int m = idx >> 5, k = idx & 31;
            ra[i] = h_in[(m0 + m) * Hn + k];
        }
#pragma unroll
        for (int i = 0; i < 8; i++) {
            int idx = tid + i * 256; int m = idx >> 5, k = idx & 31;
            Abuf[m * 32 + (k ^ ((m & 7) << 2))] = ra[i];
        }
        __syncthreads();

        for (int ch = 0; ch < 16; ch++) {
            if (ch < 15) {
                int k0 = (ch + 1) << 5;
#pragma unroll
                for (int i = 0; i < 8; i++) {
                    int idx = tid + i * 256; int m = idx >> 5, k = idx & 31;
                    ra[i] = h_in[(m0 + m) * Hn + k0 + k];
                }
            }
            const float* Ab = Abuf + (ch & 1) * 2048;
            const int choff = ch << 5;
#pragma unroll
            for (int kk = 0; kk < 32; kk += 8) {
                int c0k = (kk + tig) ^ (g << 2);
                int c1k = (kk + tig + 4) ^ (g << 2);
                float a0 = Ab[(wm + g    ) * 32 + c0k];
                float a1 = Ab[(wm + g + 8) * 32 + c0k];
                float a2 = Ab[(wm + g    ) * 32 + c1k];
                float a3 = Ab[(wm + g + 8) * 32 + c1k];
                unsigned ah0 = tf32r(a0), ah1 = tf32r(a1);
                unsigned ah2 = tf32r(a2), ah3 = tf32r(a3);
                unsigned al0 = tf32r(a0 - __uint_as_float(ah0));
                unsigned al1 = tf32r(a1 - __uint_as_float(ah1));
                unsigned al2 = tf32r(a2 - __uint_as_float(ah2));
                unsigned al3 = tf32r(a3 - __uint_as_float(ah3));
                unsigned bh[3][2], bl[3][2];
#pragma unroll
                for (int ni = 0; ni < 3; ni++) {
                    int base = (wn + ni * 8 + g) * 512 + choff;
                    bh[ni][0] = Ws_h[base + c0k]; bh[ni][1] = Ws_h[base + c1k];
                    bl[ni][0] = Ws_l[base + c0k]; bl[ni][1] = Ws_l[base + c1k];
                }
#pragma unroll
                for (int ni = 0; ni < 3; ni++) {
                    MMA(acc[ni], ah0, ah1, ah2, ah3, bl[ni][0], bl[ni][1]);
                    MMA(acc[ni], al0, al1, al2, al3, bh[ni][0], bh[ni][1]);
                    MMA(acc[ni], ah0, ah1, ah2, ah3, bh[ni][0], bh[ni][1]);
                }
            }
            if (ch < 15) {
#pragma unroll
                for (int i = 0; i < 8; i++) {
                    int idx = tid + i * 256; int m = idx >> 5, k = idx & 31;
                    Abuf[((ch + 1) & 1) * 2048 + m * 32 + (k ^ ((m & 7) << 2))] = ra[i];
                }
            }
            __syncthreads();
        }

        // stage gh tile (64x48) into smem (reuses A buffers; sync above done)
#pragma unroll
        for (int ni = 0; ni < 3; ni++) {
            int r = wm + g;
            int c = wn + ni * 8 + tig * 2;
            gh_s[r * 48 + c]           = acc[ni][0];
            gh_s[r * 48 + c + 1]       = acc[ni][1];
            gh_s[(r + 8) * 48 + c]     = acc[ni][2];
            gh_s[(r + 8) * 48 + c + 1] = acc[ni][3];
        }
        __syncthreads();

        // gate math: 64 rows x 16 cols, 4 elems/thread
#pragma unroll
        for (int i = 0; i < 4; i++) {
            int e = tid + i * 256;
            int row = e >> 4, col = e & 15;
            int b = m0 + row, jj = jj0 + col;
            const float* gi = GI + ((size_t)b * Tn + t) * H3;
            float ghr = gh_s[row * 48 + col]      + b_hh[jj];
            float ghz = gh_s[row * 48 + 16 + col] + b_hh[Hn + jj];
            float ghn = gh_s[row * 48 + 32 + col] + b_hh[2 * Hn + jj];
            float r = sigmoid_acc(gi[jj] + ghr);
            float z = sigmoid_acc(gi[Hn + jj] + ghz);
            float n = tanh_acc(fmaf(r, ghn, gi[2 * Hn + jj]));
            float ho = h_in[b * Hn + jj];
            float hv = (t < lengths[b]) ? ((1.f - z) * n + z * ho) : ho;
            h_out[b * Hn + jj] = hv;
        }

        // grid barrier (all 128 CTAs co-resident by construction)
        __syncthreads();
        if (tid == 0) {
            __threadfence();
            atomicAdd(bar, 1u);
            unsigned target = nc * (unsigned)(t + 1);
            unsigned v;
            do {
                asm volatile("ld.acquire.gpu.global.b32 %0, [%1];"
                             : "=r"(v) : "l"(bar) : "memory");
                if (v < target) __nanosleep(64);
            } while (v < target);
        }
        __syncthreads();
    }
}

// ---------------- misc -------------------------------------------------------
__global__ void init_kernel(float* h0, unsigned* bar) {
    int i = blockIdx.x * blockDim.x + threadIdx.x;
    if (i < Bn * Hn) h0[i] = 0.f;
    if (i == 0) *bar = 0u;
}

__global__ void value_kernel(const float* __restrict__ h2,
                             const float* __restrict__ Wc3,
                             const float* __restrict__ bc3,
                             float* __restrict__ out)
{
    int gw = (blockIdx.x * blockDim.x + threadIdx.x) >> 5;
    int lane = threadIdx.x & 31;
    if (gw >= Bn) return;
    float s = 0.f;
    for (int k = lane; k < Hn; k += 32) s = fmaf(h2[gw * Hn + k], Wc3[k], s);
#pragma unroll
    for (int o = 16; o; o >>= 1) s += __shfl_xor_sync(0xffffffffu, s, o);
    if (lane == 0) out[gw] = s + bc3[0];
}

// partitionable threefry bits: counter = flat index, bits = out0 ^ out1
__global__ void gumbel_kernel(unsigned k0, unsigned k1, float* __restrict__ gout)
{
    unsigned i = blockIdx.x * blockDim.x + threadIdx.x;
    unsigned o0, o1;
    threefry2x32(k0, k1, 0u, i, &o0, &o1);
    unsigned bits = o0 ^ o1;
    float f = __uint_as_float((bits >> 9) | 0x3f800000u) - 1.0f;
    float u = fmaxf(f, 1.17549435e-38f);
    float g = -log_acc(-log_acc(u));
    gout[i] = g;
}

__global__ __launch_bounds__(256)
void sample_kernel(const float* __restrict__ logits,
                   const float* __restrict__ gumbel,
                   float* __restrict__ out_query,
                   float* __restrict__ out_lp)
{
    __shared__ float red[256];
    __shared__ int   redi[256];
    int row = blockIdx.x;
    int tid = threadIdx.x;
    const float* lg = logits + (size_t)row * DICTn;
    const float* gm = gumbel + (size_t)row * DICTn;

    float l[4];
#pragma unroll
    for (int i = 0; i < 4; i++) l[i] = lg[tid + i * 256];

    float mx = fmaxf(fmaxf(l[0], l[1]), fmaxf(l[2], l[3]));
    red[tid] = mx; __syncthreads();
    for (int s = 128; s > 0; s >>= 1) {
        if (tid < s) red[tid] = fmaxf(red[tid], red[tid + s]);
        __syncthreads();
    }
    mx = red[0]; __syncthreads();

    float se = 0.f;
#pragma unroll
    for (int i = 0; i < 4; i++) se += exp_acc(l[i] - mx);
    red[tid] = se; __syncthreads();
    for (int s = 128; s > 0; s >>= 1) {
        if (tid < s) red[tid] += red[tid + s];
        __syncthreads();
    }
    float logZ = mx + log_acc(red[0]); __syncthreads();

    float bv = -1e30f; int bi = 0x7fffffff;
#pragma unroll
    for (int i = 0; i < 4; i++) {
        int idx = tid + i * 256;
        float lp = l[i] - logZ;
        out_lp[(size_t)row * DICTn + idx] = lp;
        float v = lp + gm[idx];
        if (v > bv || (v == bv && idx < bi)) { bv = v; bi = idx; }
    }
    red[tid] = bv; redi[tid] = bi; __syncthreads();
    for (int s = 128; s > 0; s >>= 1) {
        if (tid < s) {
            if (red[tid + s] > red[tid] ||
                (red[tid + s] == red[tid] && redi[tid + s] < redi[tid])) {
                red[tid] = red[tid + s]; redi[tid] = redi[tid + s];
            }
        }
        __syncthreads();
    }
    int win = redi[0];
#pragma unroll
    for (int i = 0; i < 4; i++) {
        int idx = tid + i * 256;
        out_query[(size_t)row * DICTn + idx] = (idx == win) ? 1.f : 0.f;
    }
}

// ---------------- host -------------------------------------------------------
extern "C" void kernel_launch(void* const* d_in, const int* in_sizes, int n_in,
                              void* d_out, int out_size)
{
    const float* x      = (const float*)d_in[0];
    const int*   lens   = (const int*)  d_in[1];
    const float* W_ih   = (const float*)d_in[2];
    const float* W_hh   = (const float*)d_in[3];
    const float* b_ih   = (const float*)d_in[4];
    const float* b_hh   = (const float*)d_in[5];
    const float* W_out  = (const float*)d_in[6];
    const float* b_out  = (const float*)d_in[7];
    const float* Wc1    = (const float*)d_in[8];
    const float* bc1    = (const float*)d_in[9];
    const float* Wc2    = (const float*)d_in[10];
    const float* bc2    = (const float*)d_in[11];
    const float* Wc3    = (const float*)d_in[12];
    const float* bc3    = (const float*)d_in[13];

    float* out_value = (float*)d_out;
    float* out_query = out_value + Bn;
    float* out_lp    = out_query + (size_t)NSAMP;

    float *pGI, *ph0, *pc1, *pc2, *plog, *pgum;
    unsigned* pbar;
    cudaGetSymbolAddress((void**)&pGI,  g_GI);
    cudaGetSymbolAddress((void**)&ph0,  g_h);
    cudaGetSymbolAddress((void**)&pc1,  g_c1);
    cudaGetSymbolAddress((void**)&pc2,  g_c2);
    cudaGetSymbolAddress((void**)&plog, g_logits);
    cudaGetSymbolAddress((void**)&pgum, g_gumbel);
    cudaGetSymbolAddress((void**)&pbar, g_barrier);

    const int rec_smem = (2 * WS_WORDS + 2 * 2048) * 4;   // 212992 B
    cudaFuncSetAttribute(gru_persistent,
        cudaFuncAttributeMaxDynamicSharedMemorySize, rec_smem);

    // 1) zero h0 + barrier counter
    init_kernel<<<(Bn * Hn + 255) / 256, 256>>>(ph0, pbar);

    // 2) GI = x @ W_ih^T + b_ih   [131072, 1536]  (ragged tile skip)
    gemm_f32<<<dim3(H3 / 64, BT / 128), 256>>>(x, Dn, W_ih, Dn, pGI, H3,
                                               Dn, b_ih, 0, lens);

    // 3) persistent recurrence: all 512 steps in one kernel
    gru_persistent<<<NCTA_REC, 256, rec_smem>>>(pGI, W_hh, b_hh, lens,
                                                ph0, pbar);
    float* hfin = ph0;   // (Tn even -> final hidden in buffer 0)

    // 4) critic
    gemm_f32<<<dim3(Hn / 64, Bn / 128), 256>>>(hfin, Hn, Wc1, Hn, pc1, Hn,
                                               Hn, bc1, 1, nullptr);
    gemm_f32<<<dim3(Hn / 64, Bn / 128), 256>>>(pc1, Hn, Wc2, Hn, pc2, Hn,
                                               Hn, bc2, 1, nullptr);
    value_kernel<<<(Bn * 32 + 255) / 256, 256>>>(pc2, Wc3, bc3, out_value);

    // 5) actor logits [256, 32768]
    gemm_f32<<<dim3(DICTn * Qn / 64, Bn / 128), 256>>>(hfin, Hn, W_out, Hn,
                                                       plog, DICTn * Qn,
                                                       Hn, b_out, 0, nullptr);

    // 6) gumbel noise: skey = fold_in(key(0), 1234), partitionable bits
    unsigned s0, s1;
    threefry2x32(0u, 0u, 0u, 1234u, &s0, &s1);
    gumbel_kernel<<<NSAMP / 256, 256>>>(s0, s1, pgum);

    // 7) log-softmax + categorical sample + one-hot
    sample_kernel<<<Bn * Qn, 256>>>(plog, pgum, out_query, out_lp);
}